// round 1
// baseline (speedup 1.0000x reference)
#include <cuda_runtime.h>

#define BATCH 16
#define TSEQ  4096
#define DIM   256
#define CH    64            // chunk length (timesteps per block)
#define NC    (TSEQ/CH)     // 64 chunks
#define KT    32            // K-tile

typedef unsigned long long ull;

// Scratch (allocation-free rule: __device__ globals)
__device__ float g_H[(size_t)BATCH * TSEQ * DIM];   // local-scan values (64 MB)
__device__ float g_E[BATCH * NC * DIM];             // per-chunk end-of-local-scan
__device__ float g_S[BATCH * NC * DIM];             // incoming state per chunk

__device__ __forceinline__ void ffma2(ull& d, ull a, ull b) {
    asm("fma.rn.f32x2 %0, %1, %2, %0;" : "+l"(d) : "l"(a), "l"(b));
}
__device__ __forceinline__ ull bcast2(float x) {
    ull r; asm("mov.b64 %0, {%1, %1};" : "=l"(r) : "f"(x)); return r;
}

// ---------------------------------------------------------------------------
// Kernel 1: Bu tile GEMM (64 x 256, K=256) fused with local chunk scan.
//   l_r = l_{r-1} * A + Bu_r, l_{-1} = 0. Stores l_r to g_H, l_{CH-1} to g_E.
// ---------------------------------------------------------------------------
__global__ __launch_bounds__(256, 2) void k1_gemm_scan(
    const float* __restrict__ U, const float* __restrict__ Bm,
    const float* __restrict__ A)
{
    extern __shared__ float sm[];
    float* UsT = sm;                // [KT][68]  (transposed u tile, padded)
    float* Bs  = sm + KT * 68;      // [KT][256]

    const int b   = blockIdx.y;
    const int c   = blockIdx.x;
    const int tid = threadIdx.x;
    const int tr  = tid >> 5;       // 0..7  thread row group
    const int tc  = tid & 31;       // 0..31 thread col group
    const int t0  = c * CH;
    const float* ubase = U + ((size_t)b * TSEQ + t0) * DIM;

    ull acc[8][4];
    #pragma unroll
    for (int m = 0; m < 8; ++m) {
        acc[m][0] = 0ull; acc[m][1] = 0ull; acc[m][2] = 0ull; acc[m][3] = 0ull;
    }

    for (int kk = 0; kk < DIM; kk += KT) {
        __syncthreads();
        // stage u tile transposed: UsT[k][row] = u[t0+row][kk+k]
        #pragma unroll
        for (int i = tid; i < CH * KT; i += 256) {
            int row = i >> 5, k = i & 31;
            UsT[k * 68 + row] = ubase[row * DIM + kk + k];
        }
        // stage B tile: Bs[k][s] = B[kk+k][s]
        {
            const float4* bg  = (const float4*)(Bm + (size_t)kk * DIM);
            float4*       bs4 = (float4*)Bs;
            #pragma unroll
            for (int i = tid; i < (KT * DIM) / 4; i += 256) bs4[i] = bg[i];
        }
        __syncthreads();

        #pragma unroll
        for (int k = 0; k < KT; ++k) {
            float4 a0 = *(const float4*)&UsT[k * 68 + tr * 8];
            float4 a1 = *(const float4*)&UsT[k * 68 + tr * 8 + 4];
            ull ap[8];
            ap[0] = bcast2(a0.x); ap[1] = bcast2(a0.y);
            ap[2] = bcast2(a0.z); ap[3] = bcast2(a0.w);
            ap[4] = bcast2(a1.x); ap[5] = bcast2(a1.y);
            ap[6] = bcast2(a1.z); ap[7] = bcast2(a1.w);
            const ull* brow = (const ull*)(Bs + k * DIM + tc * 8);
            ull b0 = brow[0], b1 = brow[1], b2 = brow[2], b3 = brow[3];
            #pragma unroll
            for (int m = 0; m < 8; ++m) {
                ffma2(acc[m][0], ap[m], b0);
                ffma2(acc[m][1], ap[m], b1);
                ffma2(acc[m][2], ap[m], b2);
                ffma2(acc[m][3], ap[m], b3);
            }
        }
    }

    __syncthreads();
    // dump Bu tile to smem as [64][256] for the time scan
    #pragma unroll
    for (int m = 0; m < 8; ++m) {
        ull* dst = (ull*)(sm + (tr * 8 + m) * DIM + tc * 8);
        dst[0] = acc[m][0]; dst[1] = acc[m][1];
        dst[2] = acc[m][2]; dst[3] = acc[m][3];
    }
    __syncthreads();

    // local scan: one thread per state s
    const int s = tid;
    const float a = A[s];
    float h = 0.f;
    float* hout = g_H + ((size_t)b * TSEQ + t0) * DIM + s;
    #pragma unroll 8
    for (int r = 0; r < CH; ++r) {
        h = fmaf(h, a, sm[r * DIM + s]);
        hout[(size_t)r * DIM] = h;
    }
    g_E[((size_t)b * NC + c) * DIM + s] = h;
}

// ---------------------------------------------------------------------------
// Kernel 2: cross-chunk carry scan per (b, s): s_0 = h0; s_{j+1} = A^CH*s_j + E_j
// ---------------------------------------------------------------------------
__global__ void k2_carry(const float* __restrict__ A, const float* __restrict__ h0)
{
    const int b = blockIdx.x, s = threadIdx.x;
    const float a = A[s];
    float a2 = a * a, a4 = a2 * a2, a8 = a4 * a4;
    float a16 = a8 * a8, a32 = a16 * a16, aL = a32 * a32;   // A^64, exact squarings
    float cur = h0[s];
    const size_t base = (size_t)b * NC * DIM + s;
    for (int j = 0; j < NC; ++j) {
        g_S[base + (size_t)j * DIM] = cur;
        cur = fmaf(aL, cur, g_E[base + (size_t)j * DIM]);
    }
}

// ---------------------------------------------------------------------------
// Kernel 3: h_r = A^{r+1} * s_chunk + l_r, then y tile = h @ C (64 x 256, K=256)
// ---------------------------------------------------------------------------
__global__ __launch_bounds__(256, 2) void k3_fix_gemm(
    const float* __restrict__ A, const float* __restrict__ Cm,
    float* __restrict__ Y)
{
    extern __shared__ float sm[];
    float* HT = sm;                 // [256 states][68] (state-major, padded)
    float* Cs = sm + DIM * 68;      // [KT][256]

    const int b   = blockIdx.y;
    const int c   = blockIdx.x;
    const int tid = threadIdx.x;
    const int tr  = tid >> 5;
    const int tc  = tid & 31;
    const int t0  = c * CH;

    // phase 1: reconstruct global h for this chunk into smem (transposed)
    {
        const int s = tid;
        const float a  = A[s];
        const float sj = g_S[((size_t)b * NC + c) * DIM + s];
        const float* hbase = g_H + ((size_t)b * TSEQ + t0) * DIM + s;
        float f = 1.f;
        #pragma unroll 8
        for (int r = 0; r < CH; ++r) {
            f *= a;
            HT[s * 68 + r] = fmaf(f, sj, hbase[(size_t)r * DIM]);
        }
    }

    ull acc[8][4];
    #pragma unroll
    for (int m = 0; m < 8; ++m) {
        acc[m][0] = 0ull; acc[m][1] = 0ull; acc[m][2] = 0ull; acc[m][3] = 0ull;
    }

    for (int kk = 0; kk < DIM; kk += KT) {
        __syncthreads();
        {
            const float4* cg  = (const float4*)(Cm + (size_t)kk * DIM);
            float4*       cs4 = (float4*)Cs;
            #pragma unroll
            for (int i = tid; i < (KT * DIM) / 4; i += 256) cs4[i] = cg[i];
        }
        __syncthreads();

        #pragma unroll
        for (int k = 0; k < KT; ++k) {
            // a_m = h[row = tr*8+m][state = kk+k]
            float4 a0 = *(const float4*)&HT[(kk + k) * 68 + tr * 8];
            float4 a1 = *(const float4*)&HT[(kk + k) * 68 + tr * 8 + 4];
            ull ap[8];
            ap[0] = bcast2(a0.x); ap[1] = bcast2(a0.y);
            ap[2] = bcast2(a0.z); ap[3] = bcast2(a0.w);
            ap[4] = bcast2(a1.x); ap[5] = bcast2(a1.y);
            ap[6] = bcast2(a1.z); ap[7] = bcast2(a1.w);
            const ull* crow = (const ull*)(Cs + k * DIM + tc * 8);
            ull b0 = crow[0], b1 = crow[1], b2 = crow[2], b3 = crow[3];
            #pragma unroll
            for (int m = 0; m < 8; ++m) {
                ffma2(acc[m][0], ap[m], b0);
                ffma2(acc[m][1], ap[m], b1);
                ffma2(acc[m][2], ap[m], b2);
                ffma2(acc[m][3], ap[m], b3);
            }
        }
    }

    // write y tile
    float* ybase = Y + ((size_t)b * TSEQ + t0) * DIM;
    #pragma unroll
    for (int m = 0; m < 8; ++m) {
        ull* dst = (ull*)(ybase + (size_t)(tr * 8 + m) * DIM + tc * 8);
        dst[0] = acc[m][0]; dst[1] = acc[m][1];
        dst[2] = acc[m][2]; dst[3] = acc[m][3];
    }
}

// ---------------------------------------------------------------------------

extern "C" void kernel_launch(void* const* d_in, const int* in_sizes, int n_in,
                              void* d_out, int out_size)
{
    const float* U  = (const float*)d_in[0];   // [16, 4096, 256]
    const float* A  = (const float*)d_in[1];   // [256]
    const float* Bm = (const float*)d_in[2];   // [256, 256]
    const float* Cm = (const float*)d_in[3];   // [256, 256]
    const float* h0 = (const float*)d_in[4];   // [256]
    float* Y = (float*)d_out;                  // [16, 4096, 256]

    (void)in_sizes; (void)n_in; (void)out_size;

    cudaFuncSetAttribute(k1_gemm_scan, cudaFuncAttributeMaxDynamicSharedMemorySize, 65536);
    cudaFuncSetAttribute(k3_fix_gemm,  cudaFuncAttributeMaxDynamicSharedMemorySize, 102400);

    k1_gemm_scan<<<dim3(NC, BATCH), 256, 65536>>>(U, Bm, A);
    k2_carry<<<BATCH, DIM>>>(A, h0);
    k3_fix_gemm<<<dim3(NC, BATCH), 256, 102400>>>(A, Cm, Y);
}

// round 4
// speedup vs baseline: 1.4613x; 1.4613x over previous
#include <cuda_runtime.h>
#include <cuda_bf16.h>
#include <cstdint>

#define BATCH 16
#define TSEQ  4096
#define DIM   256
#define CH    64
#define NC    (TSEQ/CH)          // 64 chunks

typedef unsigned int u32;
typedef unsigned short u16;

// ---------------- device scratch (allocation-free rule) ----------------
__device__ float g_H[(size_t)BATCH * TSEQ * DIM];   // local-scan h (64 MB)
__device__ float g_E[BATCH * NC * DIM];
__device__ float g_S[BATCH * NC * DIM];
// B / C pre-converted bf16 hi/lo in mma fragment layout:
// [variant2][kc4][kstep4][nt2_16][lane32][slot4]  (slot = ntlow*2 + breg)
// 4*4*16*32*4 = 32768 u32 per variant
__device__ u32 g_Bf[2 * 32768];
__device__ u32 g_Cf[2 * 32768];

// ---------------- helpers ----------------
__device__ __forceinline__ void split_bf16(float x, u16& hi, u16& lo) {
    __nv_bfloat16 h = __float2bfloat16_rn(x);
    __nv_bfloat16 l = __float2bfloat16_rn(x - __bfloat162float(h));
    hi = __bfloat16_as_ushort(h);
    lo = __bfloat16_as_ushort(l);
}
__device__ __forceinline__ u32 pack2(u16 a, u16 b) {
    return (u32)a | ((u32)b << 16);
}
__device__ __forceinline__ void mma_bf16(float* c, const u32* a, u32 b0, u32 b1) {
    asm("mma.sync.aligned.m16n8k16.row.col.f32.bf16.bf16.f32 "
        "{%0,%1,%2,%3}, {%4,%5,%6,%7}, {%8,%9}, {%0,%1,%2,%3};"
        : "+f"(c[0]), "+f"(c[1]), "+f"(c[2]), "+f"(c[3])
        : "r"(a[0]), "r"(a[1]), "r"(a[2]), "r"(a[3]), "r"(b0), "r"(b1));
}

// ---------------------------------------------------------------------------
// k0: convert B and C to hi/lo bf16 fragment layout. 32768 threads.
// B-frag (m16n8k16, col-major B): reg j covers k = (lane%4)*2 + j*8 + {0,1},
// n = ntile*8 + lane/4.
// ---------------------------------------------------------------------------
__global__ void k0_convert(const float* __restrict__ Bm, const float* __restrict__ Cm)
{
    int idx = blockIdx.x * 256 + threadIdx.x;        // 0..32767
    int slot  = idx & 3;
    int lane  = (idx >> 2) & 31;
    int nt2   = (idx >> 7) & 15;
    int kstep = (idx >> 11) & 3;
    int kc    = (idx >> 13) & 3;
    int ntlow = slot >> 1, breg = slot & 1;
    int n = (nt2 * 2 + ntlow) * 8 + (lane >> 2);
    int k = kc * 64 + kstep * 16 + (lane & 3) * 2 + breg * 8;

    u16 h0, l0, h1, l1;
    float b0 = Bm[(size_t)k * DIM + n], b1 = Bm[(size_t)(k + 1) * DIM + n];
    split_bf16(b0, h0, l0); split_bf16(b1, h1, l1);
    g_Bf[idx]         = pack2(h0, h1);
    g_Bf[32768 + idx] = pack2(l0, l1);

    float c0 = Cm[(size_t)k * DIM + n], c1 = Cm[(size_t)(k + 1) * DIM + n];
    split_bf16(c0, h0, l0); split_bf16(c1, h1, l1);
    g_Cf[idx]         = pack2(h0, h1);
    g_Cf[32768 + idx] = pack2(l0, l1);
}

// ---------------- smem layouts ----------------
// kA: [UH 32KB][UL 32KB][sB 64KB]   (scan buffer 64x260 floats overlays offset 0)
// kB: [scanb 66560B][UH 32KB][UL 32KB][sB 64KB]
#define KA_SMEM  (32768 + 32768 + 65536)                 // 131072
#define KB_SCAN  (64 * 260 * 4)                          // 66560
#define KB_SMEM  (KB_SCAN + 131072)                      // 197632

// A-frag staging: write one b32 frag reg from a float2 of the source row.
// frag index = ((slab*16 + kstep)*32 + lane)*4 + reg
__device__ __forceinline__ void stage_A_pair(u32* UH, u32* UL, int row, int cp,
                                             float x, float y)
{
    int slab = row >> 4, rin = row & 15;
    int kstep = cp >> 3, cpin = cp & 7;
    int lane = (rin & 7) * 4 + (cpin & 3);
    int reg  = ((cpin >> 2) << 1) | (rin >> 3);
    int a = (((slab * 16 + kstep) * 32 + lane) << 2) + reg;
    u16 hx, lx, hy, ly;
    split_bf16(x, hx, lx); split_bf16(y, hy, ly);
    UH[a] = pack2(hx, hy);
    UL[a] = pack2(lx, ly);
}

// Shared mainloop: A-frags in (UH,UL), B-frag source gBf, accumulate into acc[16][4]
__device__ __forceinline__ void gemm_main(const u32* __restrict__ gBf,
                                          u32* UH, u32* UL, u32* sB,
                                          float acc[16][4],
                                          int wr, int wc, int lane, int tid)
{
    for (int kc = 0; kc < 4; ++kc) {
        __syncthreads();
        // stage B chunk (both variants, 4096 uint4)
        {
            const uint4* src = (const uint4*)(gBf) + kc * 2048;            // hi
            const uint4* srl = (const uint4*)(gBf + 32768) + kc * 2048;    // lo
            uint4* dsh = (uint4*)sB;
            uint4* dsl = (uint4*)(sB + 8192);
            #pragma unroll
            for (int i = 0; i < 8; ++i) {
                dsh[tid + i * 256] = src[tid + i * 256];
                dsl[tid + i * 256] = srl[tid + i * 256];
            }
        }
        __syncthreads();
        #pragma unroll
        for (int kstep = 0; kstep < 4; ++kstep) {
            uint4 AH = *(const uint4*)(UH + (((wr * 16 + kc * 4 + kstep) * 32 + lane) << 2));
            uint4 AL = *(const uint4*)(UL + (((wr * 16 + kc * 4 + kstep) * 32 + lane) << 2));
            u32 ah[4] = {AH.x, AH.y, AH.z, AH.w};
            u32 al[4] = {AL.x, AL.y, AL.z, AL.w};
            #pragma unroll
            for (int nt2 = 0; nt2 < 8; ++nt2) {
                const u32* bp = sB + ((kstep * 16 + wc * 8 + nt2) * 32 + lane) * 4;
                uint4 BH = *(const uint4*)bp;
                uint4 BL = *(const uint4*)(bp + 8192);
                mma_bf16(acc[nt2 * 2 + 0], ah, BH.x, BH.y);
                mma_bf16(acc[nt2 * 2 + 1], ah, BH.z, BH.w);
                mma_bf16(acc[nt2 * 2 + 0], ah, BL.x, BL.y);
                mma_bf16(acc[nt2 * 2 + 1], ah, BL.z, BL.w);
                mma_bf16(acc[nt2 * 2 + 0], al, BH.x, BH.y);
                mma_bf16(acc[nt2 * 2 + 1], al, BH.z, BH.w);
            }
        }
    }
}

// write accumulators into scan-layout smem [row][col], row stride 260 floats
__device__ __forceinline__ void acc_to_scanb(float* scanb, float acc[16][4],
                                             int wr, int wc, int lane)
{
    int r0 = wr * 16 + (lane >> 2);
    #pragma unroll
    for (int t = 0; t < 16; ++t) {
        int col = wc * 128 + t * 8 + (lane & 3) * 2;
        scanb[r0 * 260 + col]       = acc[t][0];
        scanb[r0 * 260 + col + 1]   = acc[t][1];
        scanb[(r0 + 8) * 260 + col]     = acc[t][2];
        scanb[(r0 + 8) * 260 + col + 1] = acc[t][3];
    }
}

// ---------------------------------------------------------------------------
// kA: Bu = U @ B (bf16-split HMMA) fused with local chunk scan
// ---------------------------------------------------------------------------
__global__ __launch_bounds__(256, 1) void kA(
    const float* __restrict__ U, const float* __restrict__ A)
{
    extern __shared__ __align__(16) char smem[];
    u32* UH = (u32*)smem;
    u32* UL = UH + 8192;
    u32* sB = UL + 8192;
    float* scanb = (float*)smem;     // overlays frag region after GEMM

    const int tid = threadIdx.x, wid = tid >> 5, lane = tid & 31;
    const int wr = wid >> 1, wc = wid & 1;
    const int b = blockIdx.y, c = blockIdx.x;
    const int t0 = c * CH;

    // stage U tile as hi/lo A-fragments (coalesced float2 reads)
    {
        const float* ub = U + ((size_t)b * TSEQ + t0) * DIM;
        #pragma unroll
        for (int it = 0; it < 32; ++it) {
            int idx = tid + it * 256;          // 8192 = 64 rows x 128 colpairs
            int row = idx >> 7, cp = idx & 127;
            float2 v = *(const float2*)(ub + (size_t)row * DIM + cp * 2);
            stage_A_pair(UH, UL, row, cp, v.x, v.y);
        }
    }

    float acc[16][4];
    #pragma unroll
    for (int i = 0; i < 16; ++i) { acc[i][0]=0.f; acc[i][1]=0.f; acc[i][2]=0.f; acc[i][3]=0.f; }

    gemm_main(g_Bf, UH, UL, sB, acc, wr, wc, lane, tid);

    __syncthreads();                 // frag region dead; reuse as scan buffer
    acc_to_scanb(scanb, acc, wr, wc, lane);
    __syncthreads();

    // local scan: one thread per state
    {
        const int s = tid;
        const float a = A[s];
        float h = 0.f;
        float* hout = g_H + ((size_t)b * TSEQ + t0) * DIM + s;
        #pragma unroll 8
        for (int t = 0; t < CH; ++t) {
            h = fmaf(h, a, scanb[t * 260 + s]);
            hout[(size_t)t * DIM] = h;
        }
        g_E[((size_t)b * NC + c) * DIM + s] = h;
    }
}

// ---------------------------------------------------------------------------
// k2: cross-chunk carry scan
// ---------------------------------------------------------------------------
__global__ void k2_carry(const float* __restrict__ A, const float* __restrict__ h0)
{
    const int b = blockIdx.x, s = threadIdx.x;
    float p = A[s];
    #pragma unroll
    for (int i = 0; i < 6; ++i) p = p * p;     // a^64
    float cur = h0[s];
    const size_t base = (size_t)b * NC * DIM + s;
    for (int j = 0; j < NC; ++j) {
        g_S[base + (size_t)j * DIM] = cur;
        cur = fmaf(p, cur, g_E[base + (size_t)j * DIM]);
    }
}

// ---------------------------------------------------------------------------
// kB: h = local + A^{t+1}*carry, Y = h @ C (bf16-split HMMA)
// ---------------------------------------------------------------------------
__global__ __launch_bounds__(256, 1) void kB(
    const float* __restrict__ A, float* __restrict__ Y)
{
    extern __shared__ __align__(16) char smem[];
    float* scanb = (float*)smem;                       // 64 x 260 floats
    u32* UH = (u32*)(smem + KB_SCAN);
    u32* UL = UH + 8192;
    u32* sB = UL + 8192;

    const int tid = threadIdx.x, wid = tid >> 5, lane = tid & 31;
    const int wr = wid >> 1, wc = wid & 1;
    const int b = blockIdx.y, c = blockIdx.x;
    const int t0 = c * CH;

    // pass 1: reconstruct h for this chunk into scanb
    {
        const int s = tid;
        const float a = A[s];
        const float carry = g_S[((size_t)b * NC + c) * DIM + s];
        const float* hloc = g_H + ((size_t)b * TSEQ + t0) * DIM + s;
        float f = 1.f;
        #pragma unroll 8
        for (int t = 0; t < CH; ++t) {
            f *= a;
            scanb[t * 260 + s] = fmaf(f, carry, hloc[(size_t)t * DIM]);
        }
    }
    __syncthreads();

    // pass 2: convert scanb -> A-fragments
    #pragma unroll
    for (int it = 0; it < 32; ++it) {
        int idx = tid + it * 256;
        int row = idx >> 7, cp = idx & 127;
        float2 v = *(const float2*)(scanb + row * 260 + cp * 2);
        stage_A_pair(UH, UL, row, cp, v.x, v.y);
    }

    float acc[16][4];
    #pragma unroll
    for (int i = 0; i < 16; ++i) { acc[i][0]=0.f; acc[i][1]=0.f; acc[i][2]=0.f; acc[i][3]=0.f; }

    gemm_main(g_Cf, UH, UL, sB, acc, wr, wc, lane, tid);

    __syncthreads();
    acc_to_scanb(scanb, acc, wr, wc, lane);
    __syncthreads();

    // coalesced float4 store of Y tile
    {
        float* yb = Y + ((size_t)b * TSEQ + t0) * DIM;
        #pragma unroll
        for (int it = 0; it < 16; ++it) {
            int idx = tid + it * 256;          // 4096 = 64 rows x 64 col4s
            int row = idx >> 6, c4 = idx & 63;
            *(float4*)(yb + (size_t)row * DIM + c4 * 4) =
                *(const float4*)(scanb + row * 260 + c4 * 4);
        }
    }
}

// ---------------------------------------------------------------------------

extern "C" void kernel_launch(void* const* d_in, const int* in_sizes, int n_in,
                              void* d_out, int out_size)
{
    const float* U  = (const float*)d_in[0];
    const float* A  = (const float*)d_in[1];
    const float* Bm = (const float*)d_in[2];
    const float* Cm = (const float*)d_in[3];
    const float* h0 = (const float*)d_in[4];
    float* Y = (float*)d_out;
    (void)in_sizes; (void)n_in; (void)out_size;

    cudaFuncSetAttribute(kA, cudaFuncAttributeMaxDynamicSharedMemorySize, KA_SMEM);
    cudaFuncSetAttribute(kB, cudaFuncAttributeMaxDynamicSharedMemorySize, KB_SMEM);

    k0_convert<<<128, 256>>>(Bm, Cm);
    kA<<<dim3(NC, BATCH), 256, KA_SMEM>>>(U, A);
    k2_carry<<<BATCH, DIM>>>(A, h0);
    kB<<<dim3(NC, BATCH), 256, KB_SMEM>>>(A, Y);
}

// round 5
// speedup vs baseline: 1.5688x; 1.0735x over previous
#include <cuda_runtime.h>
#include <cuda_bf16.h>
#include <cstdint>

#define BATCH 16
#define TSEQ  4096
#define DIM   256
#define CH    64
#define NC    (TSEQ/CH)          // 64 chunks

typedef unsigned int u32;
typedef unsigned short u16;

// ---------------- device scratch (allocation-free rule) ----------------
__device__ float g_H[(size_t)BATCH * TSEQ * DIM];   // local-scan h (64 MB)
__device__ float g_E[BATCH * NC * DIM];
__device__ float g_S[BATCH * NC * DIM];
// B / C pre-converted bf16 hi/lo in mma fragment layout:
// [variant2][ks16][nt2_16][lane32][slot4]   (4*4*16*32*4 = 32768 u32 / variant)
__device__ __align__(16) u32 g_Bf[2 * 32768];
__device__ __align__(16) u32 g_Cf[2 * 32768];

// ---------------- helpers ----------------
__device__ __forceinline__ void split_bf16(float x, u16& hi, u16& lo) {
    __nv_bfloat16 h = __float2bfloat16_rn(x);
    __nv_bfloat16 l = __float2bfloat16_rn(x - __bfloat162float(h));
    hi = __bfloat16_as_ushort(h);
    lo = __bfloat16_as_ushort(l);
}
__device__ __forceinline__ u32 pack2(u16 a, u16 b) {
    return (u32)a | ((u32)b << 16);
}
__device__ __forceinline__ void mma_bf16(float* c, const u32* a, u32 b0, u32 b1) {
    asm("mma.sync.aligned.m16n8k16.row.col.f32.bf16.bf16.f32 "
        "{%0,%1,%2,%3}, {%4,%5,%6,%7}, {%8,%9}, {%0,%1,%2,%3};"
        : "+f"(c[0]), "+f"(c[1]), "+f"(c[2]), "+f"(c[3])
        : "r"(a[0]), "r"(a[1]), "r"(a[2]), "r"(a[3]), "r"(b0), "r"(b1));
}

// ---------------------------------------------------------------------------
// k0: convert B and C to hi/lo bf16 fragment layout. 32768 threads.
// ---------------------------------------------------------------------------
__global__ void k0_convert(const float* __restrict__ Bm, const float* __restrict__ Cm)
{
    int idx = blockIdx.x * 256 + threadIdx.x;        // 0..32767
    int slot  = idx & 3;
    int lane  = (idx >> 2) & 31;
    int nt2   = (idx >> 7) & 15;
    int ks    = (idx >> 11) & 15;                    // k-step 0..15
    int ntlow = slot >> 1, breg = slot & 1;
    int n = (nt2 * 2 + ntlow) * 8 + (lane >> 2);
    int k = ks * 16 + (lane & 3) * 2 + breg * 8;

    u16 h0, l0, h1, l1;
    float b0 = Bm[(size_t)k * DIM + n], b1 = Bm[(size_t)(k + 1) * DIM + n];
    split_bf16(b0, h0, l0); split_bf16(b1, h1, l1);
    g_Bf[idx]         = pack2(h0, h1);
    g_Bf[32768 + idx] = pack2(l0, l1);

    float c0 = Cm[(size_t)k * DIM + n], c1 = Cm[(size_t)(k + 1) * DIM + n];
    split_bf16(c0, h0, l0); split_bf16(c1, h1, l1);
    g_Cf[idx]         = pack2(h0, h1);
    g_Cf[32768 + idx] = pack2(l0, l1);
}

// ---------------- smem ----------------
// frag region: UH 32KB + UL 32KB = 65536; scanb (64 x 260 floats = 66560) overlays
#define SMEM_SZ  66560

// A-frag staging: frag index = ((slab*16 + ks)*32 + lane)*4 + reg
__device__ __forceinline__ void stage_A_pair(u32* UH, u32* UL, int row, int cp,
                                             float x, float y)
{
    int slab = row >> 4, rin = row & 15;
    int ks = cp >> 3, cpin = cp & 7;
    int lane = (rin & 7) * 4 + (cpin & 3);
    int reg  = ((cpin >> 2) << 1) | (rin >> 3);
    int a = (((slab * 16 + ks) * 32 + lane) << 2) + reg;
    u16 hx, lx, hy, ly;
    split_bf16(x, hx, lx); split_bf16(y, hy, ly);
    UH[a] = pack2(hx, hy);
    UL[a] = pack2(lx, ly);
}

// Mainloop: A-frags from smem, B-frags via LDG from fragment array (L2-resident).
// Warp tile m16 x n64: wr = row slab (0..3), wc = col quarter (0..3).
__device__ __forceinline__ void gemm_main(const u32* __restrict__ gBf,
                                          const u32* UH, const u32* UL,
                                          float acc[8][4], int wr, int wc, int lane)
{
    #pragma unroll
    for (int ks = 0; ks < 16; ++ks) {
        uint4 AH = *(const uint4*)(UH + (((wr * 16 + ks) * 32 + lane) << 2));
        uint4 AL = *(const uint4*)(UL + (((wr * 16 + ks) * 32 + lane) << 2));
        u32 ah[4] = {AH.x, AH.y, AH.z, AH.w};
        u32 al[4] = {AL.x, AL.y, AL.z, AL.w};
        uint4 BH[4], BL[4];
        const u32* bp = gBf + (ks * 16 + wc * 4) * 128 + lane * 4;
        #pragma unroll
        for (int j = 0; j < 4; ++j) {
            BH[j] = *(const uint4*)(bp + j * 128);
            BL[j] = *(const uint4*)(bp + 32768 + j * 128);
        }
        // three passes: acc reuse distance = 8 MMAs (no back-to-back RAW)
        #pragma unroll
        for (int j = 0; j < 4; ++j) {
            mma_bf16(acc[2*j],   ah, BH[j].x, BH[j].y);
            mma_bf16(acc[2*j+1], ah, BH[j].z, BH[j].w);
        }
        #pragma unroll
        for (int j = 0; j < 4; ++j) {
            mma_bf16(acc[2*j],   ah, BL[j].x, BL[j].y);
            mma_bf16(acc[2*j+1], ah, BL[j].z, BL[j].w);
        }
        #pragma unroll
        for (int j = 0; j < 4; ++j) {
            mma_bf16(acc[2*j],   al, BH[j].x, BH[j].y);
            mma_bf16(acc[2*j+1], al, BH[j].z, BH[j].w);
        }
    }
}

// write accumulators into scan-layout smem [row][col], row stride 260 floats
__device__ __forceinline__ void acc_to_scanb(float* scanb, float acc[8][4],
                                             int wr, int wc, int lane)
{
    int r0 = wr * 16 + (lane >> 2);
    #pragma unroll
    for (int a = 0; a < 8; ++a) {
        int col = wc * 64 + (a >> 1) * 16 + (a & 1) * 8 + (lane & 3) * 2;
        scanb[r0 * 260 + col]           = acc[a][0];
        scanb[r0 * 260 + col + 1]       = acc[a][1];
        scanb[(r0 + 8) * 260 + col]     = acc[a][2];
        scanb[(r0 + 8) * 260 + col + 1] = acc[a][3];
    }
}

// ---------------------------------------------------------------------------
// kA: Bu = U @ B (bf16-split HMMA) fused with local chunk scan. 512 threads.
// ---------------------------------------------------------------------------
__global__ __launch_bounds__(512, 1) void kA(
    const float* __restrict__ U, const float* __restrict__ A)
{
    extern __shared__ __align__(16) char smem[];
    u32* UH = (u32*)smem;
    u32* UL = UH + 8192;
    float* scanb = (float*)smem;     // overlays frag region after GEMM

    const int tid = threadIdx.x, wid = tid >> 5, lane = tid & 31;
    const int wr = wid & 3, wc = wid >> 2;
    const int b = blockIdx.y, c = blockIdx.x;
    const int t0 = c * CH;

    // stage U tile as hi/lo A-fragments (coalesced float2 reads)
    {
        const float* ub = U + ((size_t)b * TSEQ + t0) * DIM;
        #pragma unroll
        for (int it = 0; it < 16; ++it) {
            int idx = tid + it * 512;          // 8192 = 64 rows x 128 colpairs
            int row = idx >> 7, cp = idx & 127;
            float2 v = *(const float2*)(ub + (size_t)row * DIM + cp * 2);
            stage_A_pair(UH, UL, row, cp, v.x, v.y);
        }
    }
    __syncthreads();

    float acc[8][4];
    #pragma unroll
    for (int i = 0; i < 8; ++i) { acc[i][0]=0.f; acc[i][1]=0.f; acc[i][2]=0.f; acc[i][3]=0.f; }

    gemm_main(g_Bf, UH, UL, acc, wr, wc, lane);

    __syncthreads();                 // frag region dead; reuse as scan buffer
    acc_to_scanb(scanb, acc, wr, wc, lane);
    __syncthreads();

    // local scan: one thread per state (first 256 threads)
    if (tid < 256) {
        const int s = tid;
        const float a = A[s];
        float h = 0.f;
        float* hout = g_H + ((size_t)b * TSEQ + t0) * DIM + s;
        #pragma unroll 8
        for (int t = 0; t < CH; ++t) {
            h = fmaf(h, a, scanb[t * 260 + s]);
            hout[(size_t)t * DIM] = h;
        }
        g_E[((size_t)b * NC + c) * DIM + s] = h;
    }
}

// ---------------------------------------------------------------------------
// k2: cross-chunk carry scan
// ---------------------------------------------------------------------------
__global__ void k2_carry(const float* __restrict__ A, const float* __restrict__ h0)
{
    const int b = blockIdx.x, s = threadIdx.x;
    float p = A[s];
    #pragma unroll
    for (int i = 0; i < 6; ++i) p = p * p;     // a^64
    float cur = h0[s];
    const size_t base = (size_t)b * NC * DIM + s;
    for (int j = 0; j < NC; ++j) {
        g_S[base + (size_t)j * DIM] = cur;
        cur = fmaf(p, cur, g_E[base + (size_t)j * DIM]);
    }
}

// ---------------------------------------------------------------------------
// kB: h = local + A^{t+1}*carry (direct to frags), Y = h @ C. 512 threads.
// ---------------------------------------------------------------------------
__global__ __launch_bounds__(512, 1) void kB(
    const float* __restrict__ A, float* __restrict__ Y)
{
    extern __shared__ __align__(16) char smem[];
    u32* UH = (u32*)smem;
    u32* UL = UH + 8192;
    float* scanb = (float*)smem;     // overlays frag region after GEMM

    const int tid = threadIdx.x, wid = tid >> 5, lane = tid & 31;
    const int wr = wid & 3, wc = wid >> 2;
    const int b = blockIdx.y, c = blockIdx.x;
    const int t0 = c * CH;

    // pass 1: reconstruct h for this chunk, write straight into A-frag layout.
    // thread (tid<128) owns state pair (2*tid, 2*tid+1); rows = time.
    if (tid < 128) {
        const float2 a2 = *(const float2*)(A + 2 * tid);
        const float2 cr = *(const float2*)(g_S + ((size_t)b * NC + c) * DIM + 2 * tid);
        const float* hloc = g_H + ((size_t)b * TSEQ + t0) * DIM + 2 * tid;
        float fx = 1.f, fy = 1.f;
        #pragma unroll 4
        for (int t = 0; t < CH; ++t) {
            fx *= a2.x; fy *= a2.y;
            float2 hl = *(const float2*)(hloc + (size_t)t * DIM);
            stage_A_pair(UH, UL, t, tid,
                         fmaf(fx, cr.x, hl.x), fmaf(fy, cr.y, hl.y));
        }
    }
    __syncthreads();

    float acc[8][4];
    #pragma unroll
    for (int i = 0; i < 8; ++i) { acc[i][0]=0.f; acc[i][1]=0.f; acc[i][2]=0.f; acc[i][3]=0.f; }

    gemm_main(g_Cf, UH, UL, acc, wr, wc, lane);

    __syncthreads();
    acc_to_scanb(scanb, acc, wr, wc, lane);
    __syncthreads();

    // coalesced float4 store of Y tile
    {
        float* yb = Y + ((size_t)b * TSEQ + t0) * DIM;
        #pragma unroll
        for (int it = 0; it < 8; ++it) {
            int idx = tid + it * 512;          // 4096 = 64 rows x 64 col4s
            int row = idx >> 6, c4 = idx & 63;
            *(float4*)(yb + (size_t)row * DIM + c4 * 4) =
                *(const float4*)(scanb + row * 260 + c4 * 4);
        }
    }
}

// ---------------------------------------------------------------------------

extern "C" void kernel_launch(void* const* d_in, const int* in_sizes, int n_in,
                              void* d_out, int out_size)
{
    const float* U  = (const float*)d_in[0];
    const float* A  = (const float*)d_in[1];
    const float* Bm = (const float*)d_in[2];
    const float* Cm = (const float*)d_in[3];
    const float* h0 = (const float*)d_in[4];
    float* Y = (float*)d_out;
    (void)in_sizes; (void)n_in; (void)out_size;

    cudaFuncSetAttribute(kA, cudaFuncAttributeMaxDynamicSharedMemorySize, SMEM_SZ);
    cudaFuncSetAttribute(kB, cudaFuncAttributeMaxDynamicSharedMemorySize, SMEM_SZ);

    k0_convert<<<128, 256>>>(Bm, Cm);
    kA<<<dim3(NC, BATCH), 512, SMEM_SZ>>>(U, A);
    k2_carry<<<BATCH, DIM>>>(A, h0);
    kB<<<dim3(NC, BATCH), 512, SMEM_SZ>>>(A, Y);
}

// round 6
// speedup vs baseline: 1.9535x; 1.2452x over previous
#include <cuda_runtime.h>
#include <cuda_bf16.h>
#include <cstdint>

#define BATCH 16
#define TSEQ  4096
#define DIM   256
#define CH    64
#define NC    (TSEQ/CH)          // 64 chunks

typedef unsigned int u32;
typedef unsigned short u16;

// ---------------- device scratch (allocation-free rule) ----------------
__device__ float g_H[(size_t)BATCH * TSEQ * DIM];   // local-scan h (64 MB)
__device__ float g_E[BATCH * NC * DIM];
__device__ float g_S[BATCH * NC * DIM];
// B / C pre-converted bf16 hi/lo in mma fragment layout:
// [variant2][ks16][nt2_16][lane32][slot4]   (16*16*32*4 = 32768 u32 / variant)
__device__ __align__(16) u32 g_Bf[2 * 32768];
__device__ __align__(16) u32 g_Cf[2 * 32768];

// ---------------- helpers ----------------
__device__ __forceinline__ void split_bf16(float x, u16& hi, u16& lo) {
    __nv_bfloat16 h = __float2bfloat16_rn(x);
    __nv_bfloat16 l = __float2bfloat16_rn(x - __bfloat162float(h));
    hi = __bfloat16_as_ushort(h);
    lo = __bfloat16_as_ushort(l);
}
__device__ __forceinline__ u32 pack2(u16 a, u16 b) {
    return (u32)a | ((u32)b << 16);
}
__device__ __forceinline__ void mma_bf16(float* c, const u32* a, u32 b0, u32 b1) {
    asm("mma.sync.aligned.m16n8k16.row.col.f32.bf16.bf16.f32 "
        "{%0,%1,%2,%3}, {%4,%5,%6,%7}, {%8,%9}, {%0,%1,%2,%3};"
        : "+f"(c[0]), "+f"(c[1]), "+f"(c[2]), "+f"(c[3])
        : "r"(a[0]), "r"(a[1]), "r"(a[2]), "r"(a[3]), "r"(b0), "r"(b1));
}

// ---------------------------------------------------------------------------
// k0: convert B and C to hi/lo bf16 fragment layout. 32768 threads.
// ---------------------------------------------------------------------------
__global__ void k0_convert(const float* __restrict__ Bm, const float* __restrict__ Cm)
{
    int idx = blockIdx.x * 256 + threadIdx.x;        // 0..32767
    int slot  = idx & 3;
    int lane  = (idx >> 2) & 31;
    int nt2   = (idx >> 7) & 15;
    int ks    = (idx >> 11) & 15;                    // k-step 0..15
    int ntlow = slot >> 1, breg = slot & 1;
    int n = (nt2 * 2 + ntlow) * 8 + (lane >> 2);
    int k = ks * 16 + (lane & 3) * 2 + breg * 8;

    u16 h0, l0, h1, l1;
    float b0 = Bm[(size_t)k * DIM + n], b1 = Bm[(size_t)(k + 1) * DIM + n];
    split_bf16(b0, h0, l0); split_bf16(b1, h1, l1);
    g_Bf[idx]         = pack2(h0, h1);
    g_Bf[32768 + idx] = pack2(l0, l1);

    float c0 = Cm[(size_t)k * DIM + n], c1 = Cm[(size_t)(k + 1) * DIM + n];
    split_bf16(c0, h0, l0); split_bf16(c1, h1, l1);
    g_Cf[idx]         = pack2(h0, h1);
    g_Cf[32768 + idx] = pack2(l0, l1);
}

// ---------------- smem ----------------
// frag region: UH 32KB + UL 32KB = 65536; scanb (64 x 260 floats = 66560) overlays
#define SMEM_SZ  66560

// A-frag staging: frag index = ((slab*16 + ks)*32 + lane)*4 + reg
__device__ __forceinline__ void stage_A_pair(u32* UH, u32* UL, int row, int cp,
                                             float x, float y)
{
    int slab = row >> 4, rin = row & 15;
    int ks = cp >> 3, cpin = cp & 7;
    int lane = (rin & 7) * 4 + (cpin & 3);
    int reg  = ((cpin >> 2) << 1) | (rin >> 3);
    int a = (((slab * 16 + ks) * 32 + lane) << 2) + reg;
    u16 hx, lx, hy, ly;
    split_bf16(x, hx, lx); split_bf16(y, hy, ly);
    UH[a] = pack2(hx, hy);
    UL[a] = pack2(lx, ly);
}

// Mainloop, register-lean: A-frags from smem, B-frags JIT via LDG (L2-resident).
// Warp tile m16 x n64: wr = row slab (0..3), wc = col quarter (0..3).
__device__ __forceinline__ void gemm_main(const u32* __restrict__ gBf,
                                          const u32* UH, const u32* UL,
                                          float acc[8][4], int wr, int wc, int lane)
{
    const u32* ah_p = UH + (((wr * 16) * 32 + lane) << 2);
    const u32* al_p = UL + (((wr * 16) * 32 + lane) << 2);
    const u32* b_p  = gBf + (wc * 4) * 128 + lane * 4;
    #pragma unroll
    for (int ks = 0; ks < 16; ++ks) {
        uint4 AH = *(const uint4*)(ah_p + ks * 128);
        uint4 AL = *(const uint4*)(al_p + ks * 128);
        u32 ah[4] = {AH.x, AH.y, AH.z, AH.w};
        u32 al[4] = {AL.x, AL.y, AL.z, AL.w};
        const u32* bp = b_p + ks * 2048;
        #pragma unroll
        for (int jp = 0; jp < 2; ++jp) {
            uint4 BH0 = *(const uint4*)(bp + (2 * jp) * 128);
            uint4 BH1 = *(const uint4*)(bp + (2 * jp + 1) * 128);
            uint4 BL0 = *(const uint4*)(bp + 32768 + (2 * jp) * 128);
            uint4 BL1 = *(const uint4*)(bp + 32768 + (2 * jp + 1) * 128);
            float* a0 = acc[4 * jp + 0];
            float* a1 = acc[4 * jp + 1];
            float* a2 = acc[4 * jp + 2];
            float* a3 = acc[4 * jp + 3];
            // three passes, acc reuse distance 4
            mma_bf16(a0, ah, BH0.x, BH0.y);
            mma_bf16(a1, ah, BH0.z, BH0.w);
            mma_bf16(a2, ah, BH1.x, BH1.y);
            mma_bf16(a3, ah, BH1.z, BH1.w);
            mma_bf16(a0, ah, BL0.x, BL0.y);
            mma_bf16(a1, ah, BL0.z, BL0.w);
            mma_bf16(a2, ah, BL1.x, BL1.y);
            mma_bf16(a3, ah, BL1.z, BL1.w);
            mma_bf16(a0, al, BH0.x, BH0.y);
            mma_bf16(a1, al, BH0.z, BH0.w);
            mma_bf16(a2, al, BH1.x, BH1.y);
            mma_bf16(a3, al, BH1.z, BH1.w);
        }
    }
}

// write accumulators into scan-layout smem [row][col], row stride 260 floats
__device__ __forceinline__ void acc_to_scanb(float* scanb, float acc[8][4],
                                             int wr, int wc, int lane)
{
    int r0 = wr * 16 + (lane >> 2);
    #pragma unroll
    for (int a = 0; a < 8; ++a) {
        int col = wc * 64 + (a >> 1) * 16 + (a & 1) * 8 + (lane & 3) * 2;
        scanb[r0 * 260 + col]           = acc[a][0];
        scanb[r0 * 260 + col + 1]       = acc[a][1];
        scanb[(r0 + 8) * 260 + col]     = acc[a][2];
        scanb[(r0 + 8) * 260 + col + 1] = acc[a][3];
    }
}

// ---------------------------------------------------------------------------
// kA: Bu = U @ B (bf16-split HMMA) fused with local chunk scan. 512 thr, 2 CTA/SM.
// ---------------------------------------------------------------------------
__global__ __launch_bounds__(512, 2) void kA(
    const float* __restrict__ U, const float* __restrict__ A)
{
    extern __shared__ __align__(16) char smem[];
    u32* UH = (u32*)smem;
    u32* UL = UH + 8192;
    float* scanb = (float*)smem;     // overlays frag region after GEMM

    const int tid = threadIdx.x, wid = tid >> 5, lane = tid & 31;
    const int wr = wid & 3, wc = wid >> 2;
    const int b = blockIdx.y, c = blockIdx.x;
    const int t0 = c * CH;

    // stage U tile as hi/lo A-fragments (coalesced float2 reads)
    {
        const float* ub = U + ((size_t)b * TSEQ + t0) * DIM;
        #pragma unroll
        for (int it = 0; it < 16; ++it) {
            int idx = tid + it * 512;          // 8192 = 64 rows x 128 colpairs
            int row = idx >> 7, cp = idx & 127;
            float2 v = *(const float2*)(ub + (size_t)row * DIM + cp * 2);
            stage_A_pair(UH, UL, row, cp, v.x, v.y);
        }
    }
    __syncthreads();

    float acc[8][4];
    #pragma unroll
    for (int i = 0; i < 8; ++i) { acc[i][0]=0.f; acc[i][1]=0.f; acc[i][2]=0.f; acc[i][3]=0.f; }

    gemm_main(g_Bf, UH, UL, acc, wr, wc, lane);

    __syncthreads();                 // frag region dead; reuse as scan buffer
    acc_to_scanb(scanb, acc, wr, wc, lane);
    __syncthreads();

    // local scan: one thread per state (first 256 threads)
    if (tid < 256) {
        const int s = tid;
        const float a = A[s];
        float h = 0.f;
        float* hout = g_H + ((size_t)b * TSEQ + t0) * DIM + s;
        #pragma unroll 8
        for (int t = 0; t < CH; ++t) {
            h = fmaf(h, a, scanb[t * 260 + s]);
            hout[(size_t)t * DIM] = h;
        }
        g_E[((size_t)b * NC + c) * DIM + s] = h;
    }
}

// ---------------------------------------------------------------------------
// k2: cross-chunk carry scan
// ---------------------------------------------------------------------------
__global__ void k2_carry(const float* __restrict__ A, const float* __restrict__ h0)
{
    const int b = blockIdx.x, s = threadIdx.x;
    float p = A[s];
    #pragma unroll
    for (int i = 0; i < 6; ++i) p = p * p;     // a^64
    float cur = h0[s];
    const size_t base = (size_t)b * NC * DIM + s;
    for (int j = 0; j < NC; ++j) {
        g_S[base + (size_t)j * DIM] = cur;
        cur = fmaf(p, cur, g_E[base + (size_t)j * DIM]);
    }
}

// ---------------------------------------------------------------------------
// kB: h = local + A^{t+1}*carry (direct to frags), Y = h @ C. 512 thr, 2 CTA/SM.
// ---------------------------------------------------------------------------
__global__ __launch_bounds__(512, 2) void kB(
    const float* __restrict__ A, float* __restrict__ Y)
{
    extern __shared__ __align__(16) char smem[];
    u32* UH = (u32*)smem;
    u32* UL = UH + 8192;
    float* scanb = (float*)smem;     // overlays frag region after GEMM

    const int tid = threadIdx.x, wid = tid >> 5, lane = tid & 31;
    const int wr = wid & 3, wc = wid >> 2;
    const int b = blockIdx.y, c = blockIdx.x;
    const int t0 = c * CH;

    // pass 1: reconstruct h for this chunk, write straight into A-frag layout.
    // thread (tid<128) owns state pair (2*tid, 2*tid+1); rows = time.
    if (tid < 128) {
        const float2 a2 = *(const float2*)(A + 2 * tid);
        const float2 cr = *(const float2*)(g_S + ((size_t)b * NC + c) * DIM + 2 * tid);
        const float* hloc = g_H + ((size_t)b * TSEQ + t0) * DIM + 2 * tid;
        float fx = 1.f, fy = 1.f;
        #pragma unroll 4
        for (int t = 0; t < CH; ++t) {
            fx *= a2.x; fy *= a2.y;
            float2 hl = *(const float2*)(hloc + (size_t)t * DIM);
            stage_A_pair(UH, UL, t, tid,
                         fmaf(fx, cr.x, hl.x), fmaf(fy, cr.y, hl.y));
        }
    }
    __syncthreads();

    float acc[8][4];
    #pragma unroll
    for (int i = 0; i < 8; ++i) { acc[i][0]=0.f; acc[i][1]=0.f; acc[i][2]=0.f; acc[i][3]=0.f; }

    gemm_main(g_Cf, UH, UL, acc, wr, wc, lane);

    __syncthreads();
    acc_to_scanb(scanb, acc, wr, wc, lane);
    __syncthreads();

    // coalesced float4 store of Y tile
    {
        float* yb = Y + ((size_t)b * TSEQ + t0) * DIM;
        #pragma unroll
        for (int it = 0; it < 8; ++it) {
            int idx = tid + it * 512;          // 4096 = 64 rows x 64 col4s
            int row = idx >> 6, c4 = idx & 63;
            *(float4*)(yb + (size_t)row * DIM + c4 * 4) =
                *(const float4*)(scanb + row * 260 + c4 * 4);
        }
    }
}

// ---------------------------------------------------------------------------

extern "C" void kernel_launch(void* const* d_in, const int* in_sizes, int n_in,
                              void* d_out, int out_size)
{
    const float* U  = (const float*)d_in[0];
    const float* A  = (const float*)d_in[1];
    const float* Bm = (const float*)d_in[2];
    const float* Cm = (const float*)d_in[3];
    const float* h0 = (const float*)d_in[4];
    float* Y = (float*)d_out;
    (void)in_sizes; (void)n_in; (void)out_size;

    cudaFuncSetAttribute(kA, cudaFuncAttributeMaxDynamicSharedMemorySize, SMEM_SZ);
    cudaFuncSetAttribute(kB, cudaFuncAttributeMaxDynamicSharedMemorySize, SMEM_SZ);

    k0_convert<<<128, 256>>>(Bm, Cm);
    kA<<<dim3(NC, BATCH), 512, SMEM_SZ>>>(U, A);
    k2_carry<<<BATCH, DIM>>>(A, h0);
    kB<<<dim3(NC, BATCH), 512, SMEM_SZ>>>(A, Y);
}

// round 7
// speedup vs baseline: 2.2082x; 1.1304x over previous
#include <cuda_runtime.h>
#include <cuda_bf16.h>
#include <cstdint>

#define BATCH 16
#define TSEQ  4096
#define DIM   256
#define CH    64
#define NC    (TSEQ/CH)          // 64 chunks

typedef unsigned int u32;
typedef unsigned short u16;

// ---------------- device scratch (allocation-free rule) ----------------
__device__ float g_H[(size_t)BATCH * TSEQ * DIM];   // local-scan h (64 MB)
__device__ float g_E[BATCH * NC * DIM];
__device__ float g_S[BATCH * NC * DIM];
// B / C pre-converted bf16 hi/lo in mma fragment layout:
// [variant2][ks16][nt2_16][lane32][slot4]   (16*16*32*4 = 32768 u32 / variant)
__device__ __align__(16) u32 g_Bf[2 * 32768];
__device__ __align__(16) u32 g_Cf[2 * 32768];

// ---------------- helpers ----------------
__device__ __forceinline__ void split_bf16(float x, u16& hi, u16& lo) {
    __nv_bfloat16 h = __float2bfloat16_rn(x);
    __nv_bfloat16 l = __float2bfloat16_rn(x - __bfloat162float(h));
    hi = __bfloat16_as_ushort(h);
    lo = __bfloat16_as_ushort(l);
}
__device__ __forceinline__ u32 pack2(u16 a, u16 b) {
    return (u32)a | ((u32)b << 16);
}
__device__ __forceinline__ void mma_bf16(float* c, const u32* a, u32 b0, u32 b1) {
    asm("mma.sync.aligned.m16n8k16.row.col.f32.bf16.bf16.f32 "
        "{%0,%1,%2,%3}, {%4,%5,%6,%7}, {%8,%9}, {%0,%1,%2,%3};"
        : "+f"(c[0]), "+f"(c[1]), "+f"(c[2]), "+f"(c[3])
        : "r"(a[0]), "r"(a[1]), "r"(a[2]), "r"(a[3]), "r"(b0), "r"(b1));
}

// ---------------------------------------------------------------------------
// k0: convert B and C to hi/lo bf16 fragment layout. 32768 threads.
// ---------------------------------------------------------------------------
__global__ void k0_convert(const float* __restrict__ Bm, const float* __restrict__ Cm)
{
    int idx = blockIdx.x * 256 + threadIdx.x;        // 0..32767
    int slot  = idx & 3;
    int lane  = (idx >> 2) & 31;
    int nt2   = (idx >> 7) & 15;
    int ks    = (idx >> 11) & 15;                    // k-step 0..15
    int ntlow = slot >> 1, breg = slot & 1;
    int n = (nt2 * 2 + ntlow) * 8 + (lane >> 2);
    int k = ks * 16 + (lane & 3) * 2 + breg * 8;

    u16 h0, l0, h1, l1;
    float b0 = Bm[(size_t)k * DIM + n], b1 = Bm[(size_t)(k + 1) * DIM + n];
    split_bf16(b0, h0, l0); split_bf16(b1, h1, l1);
    g_Bf[idx]         = pack2(h0, h1);
    g_Bf[32768 + idx] = pack2(l0, l1);

    float c0 = Cm[(size_t)k * DIM + n], c1 = Cm[(size_t)(k + 1) * DIM + n];
    split_bf16(c0, h0, l0); split_bf16(c1, h1, l1);
    g_Cf[idx]         = pack2(h0, h1);
    g_Cf[32768 + idx] = pack2(l0, l1);
}

// ---------------- smem ----------------
// frag region: UH 32KB + UL 32KB = 65536; scanb (64 x 260 floats = 66560) overlays
#define SMEM_SZ  66560

// A-frag staging: frag index = ((slab*16 + ks)*32 + lane)*4 + reg
__device__ __forceinline__ void stage_A_pair(u32* UH, u32* UL, int row, int cp,
                                             float x, float y)
{
    int slab = row >> 4, rin = row & 15;
    int ks = cp >> 3, cpin = cp & 7;
    int lane = (rin & 7) * 4 + (cpin & 3);
    int reg  = ((cpin >> 2) << 1) | (rin >> 3);
    int a = (((slab * 16 + ks) * 32 + lane) << 2) + reg;
    u16 hx, lx, hy, ly;
    split_bf16(x, hx, lx); split_bf16(y, hy, ly);
    UH[a] = pack2(hx, hy);
    UL[a] = pack2(lx, ly);
}

// Mainloop: warp tile m32 x n64 (2 M-slabs), B-frags JIT via LDG (L1/L2-resident).
// wr = slab pair (0..1), wc = col quarter (0..3). 48 MMAs per warp per ks.
__device__ __forceinline__ void gemm_main(const u32* __restrict__ gBf,
                                          const u32* UH, const u32* UL,
                                          float acc[2][8][4], int wr, int wc, int lane)
{
    const u32* ah0_p = UH + ((((wr * 2 + 0) * 16) * 32 + lane) << 2);
    const u32* ah1_p = UH + ((((wr * 2 + 1) * 16) * 32 + lane) << 2);
    const u32* al0_p = UL + ((((wr * 2 + 0) * 16) * 32 + lane) << 2);
    const u32* al1_p = UL + ((((wr * 2 + 1) * 16) * 32 + lane) << 2);
    const u32* b_p   = gBf + (wc * 4) * 128 + lane * 4;
    #pragma unroll
    for (int ks = 0; ks < 16; ++ks) {
        uint4 AH0 = *(const uint4*)(ah0_p + ks * 128);
        uint4 AL0 = *(const uint4*)(al0_p + ks * 128);
        uint4 AH1 = *(const uint4*)(ah1_p + ks * 128);
        uint4 AL1 = *(const uint4*)(al1_p + ks * 128);
        u32 ah[2][4] = {{AH0.x, AH0.y, AH0.z, AH0.w}, {AH1.x, AH1.y, AH1.z, AH1.w}};
        u32 al[2][4] = {{AL0.x, AL0.y, AL0.z, AL0.w}, {AL1.x, AL1.y, AL1.z, AL1.w}};
        const u32* bp = b_p + ks * 2048;
        #pragma unroll
        for (int jp = 0; jp < 2; ++jp) {
            uint4 BH0 = *(const uint4*)(bp + (2 * jp) * 128);
            uint4 BH1 = *(const uint4*)(bp + (2 * jp + 1) * 128);
            uint4 BL0 = *(const uint4*)(bp + 32768 + (2 * jp) * 128);
            uint4 BL1 = *(const uint4*)(bp + 32768 + (2 * jp + 1) * 128);
            #pragma unroll
            for (int s = 0; s < 2; ++s) {
                float* a0 = acc[s][4 * jp + 0];
                float* a1 = acc[s][4 * jp + 1];
                float* a2 = acc[s][4 * jp + 2];
                float* a3 = acc[s][4 * jp + 3];
                // three passes, acc reuse distance 4
                mma_bf16(a0, ah[s], BH0.x, BH0.y);
                mma_bf16(a1, ah[s], BH0.z, BH0.w);
                mma_bf16(a2, ah[s], BH1.x, BH1.y);
                mma_bf16(a3, ah[s], BH1.z, BH1.w);
                mma_bf16(a0, ah[s], BL0.x, BL0.y);
                mma_bf16(a1, ah[s], BL0.z, BL0.w);
                mma_bf16(a2, ah[s], BL1.x, BL1.y);
                mma_bf16(a3, ah[s], BL1.z, BL1.w);
                mma_bf16(a0, al[s], BH0.x, BH0.y);
                mma_bf16(a1, al[s], BH0.z, BH0.w);
                mma_bf16(a2, al[s], BH1.x, BH1.y);
                mma_bf16(a3, al[s], BH1.z, BH1.w);
            }
        }
    }
}

// write accumulators into scan-layout smem [row][col], row stride 260 floats
__device__ __forceinline__ void acc_to_scanb(float* scanb, float acc[2][8][4],
                                             int wr, int wc, int lane)
{
    #pragma unroll
    for (int s = 0; s < 2; ++s) {
        int r0 = (wr * 2 + s) * 16 + (lane >> 2);
        #pragma unroll
        for (int a = 0; a < 8; ++a) {
            int col = wc * 64 + (a >> 1) * 16 + (a & 1) * 8 + (lane & 3) * 2;
            scanb[r0 * 260 + col]           = acc[s][a][0];
            scanb[r0 * 260 + col + 1]       = acc[s][a][1];
            scanb[(r0 + 8) * 260 + col]     = acc[s][a][2];
            scanb[(r0 + 8) * 260 + col + 1] = acc[s][a][3];
        }
    }
}

// ---------------------------------------------------------------------------
// kA: Bu = U @ B (bf16-split HMMA) fused with local chunk scan. 256 thr, 2 CTA/SM.
// ---------------------------------------------------------------------------
__global__ __launch_bounds__(256, 2) void kA(
    const float* __restrict__ U, const float* __restrict__ A)
{
    extern __shared__ __align__(16) char smem[];
    u32* UH = (u32*)smem;
    u32* UL = UH + 8192;
    float* scanb = (float*)smem;     // overlays frag region after GEMM

    const int tid = threadIdx.x, wid = tid >> 5, lane = tid & 31;
    const int wr = wid & 1, wc = wid >> 1;
    const int b = blockIdx.y, c = blockIdx.x;
    const int t0 = c * CH;

    // stage U tile as hi/lo A-fragments (coalesced float2 reads)
    {
        const float* ub = U + ((size_t)b * TSEQ + t0) * DIM;
        #pragma unroll
        for (int it = 0; it < 32; ++it) {
            int idx = tid + it * 256;          // 8192 = 64 rows x 128 colpairs
            int row = idx >> 7, cp = idx & 127;
            float2 v = *(const float2*)(ub + (size_t)row * DIM + cp * 2);
            stage_A_pair(UH, UL, row, cp, v.x, v.y);
        }
    }
    __syncthreads();

    float acc[2][8][4];
    #pragma unroll
    for (int s = 0; s < 2; ++s)
        #pragma unroll
        for (int i = 0; i < 8; ++i) {
            acc[s][i][0]=0.f; acc[s][i][1]=0.f; acc[s][i][2]=0.f; acc[s][i][3]=0.f;
        }

    gemm_main(g_Bf, UH, UL, acc, wr, wc, lane);

    __syncthreads();                 // frag region dead; reuse as scan buffer
    acc_to_scanb(scanb, acc, wr, wc, lane);
    __syncthreads();

    // local scan: one thread per state
    {
        const int s = tid;
        const float a = A[s];
        float h = 0.f;
        float* hout = g_H + ((size_t)b * TSEQ + t0) * DIM + s;
        #pragma unroll 8
        for (int t = 0; t < CH; ++t) {
            h = fmaf(h, a, scanb[t * 260 + s]);
            hout[(size_t)t * DIM] = h;
        }
        g_E[((size_t)b * NC + c) * DIM + s] = h;
    }
}

// ---------------------------------------------------------------------------
// k2: cross-chunk carry scan
// ---------------------------------------------------------------------------
__global__ void k2_carry(const float* __restrict__ A, const float* __restrict__ h0)
{
    const int b = blockIdx.x, s = threadIdx.x;
    float p = A[s];
    #pragma unroll
    for (int i = 0; i < 6; ++i) p = p * p;     // a^64
    float cur = h0[s];
    const size_t base = (size_t)b * NC * DIM + s;
    for (int j = 0; j < NC; ++j) {
        g_S[base + (size_t)j * DIM] = cur;
        cur = fmaf(p, cur, g_E[base + (size_t)j * DIM]);
    }
}

// ---------------------------------------------------------------------------
// kB: h = local + A^{t+1}*carry (direct to frags), Y = h @ C. 256 thr, 2 CTA/SM.
// ---------------------------------------------------------------------------
__global__ __launch_bounds__(256, 2) void kB(
    const float* __restrict__ A, float* __restrict__ Y)
{
    extern __shared__ __align__(16) char smem[];
    u32* UH = (u32*)smem;
    u32* UL = UH + 8192;
    float* scanb = (float*)smem;     // overlays frag region after GEMM

    const int tid = threadIdx.x, wid = tid >> 5, lane = tid & 31;
    const int wr = wid & 1, wc = wid >> 1;
    const int b = blockIdx.y, c = blockIdx.x;
    const int t0 = c * CH;

    // pass 1: reconstruct h for this chunk, write straight into A-frag layout.
    // thread (tid<128) owns state pair (2*tid, 2*tid+1); rows = time.
    if (tid < 128) {
        const float2 a2 = *(const float2*)(A + 2 * tid);
        const float2 cr = *(const float2*)(g_S + ((size_t)b * NC + c) * DIM + 2 * tid);
        const float* hloc = g_H + ((size_t)b * TSEQ + t0) * DIM + 2 * tid;
        float fx = 1.f, fy = 1.f;
        #pragma unroll 4
        for (int t = 0; t < CH; ++t) {
            fx *= a2.x; fy *= a2.y;
            float2 hl = *(const float2*)(hloc + (size_t)t * DIM);
            stage_A_pair(UH, UL, t, tid,
                         fmaf(fx, cr.x, hl.x), fmaf(fy, cr.y, hl.y));
        }
    }
    __syncthreads();

    float acc[2][8][4];
    #pragma unroll
    for (int s = 0; s < 2; ++s)
        #pragma unroll
        for (int i = 0; i < 8; ++i) {
            acc[s][i][0]=0.f; acc[s][i][1]=0.f; acc[s][i][2]=0.f; acc[s][i][3]=0.f;
        }

    gemm_main(g_Cf, UH, UL, acc, wr, wc, lane);

    __syncthreads();
    acc_to_scanb(scanb, acc, wr, wc, lane);
    __syncthreads();

    // coalesced float4 store of Y tile
    {
        float* yb = Y + ((size_t)b * TSEQ + t0) * DIM;
        #pragma unroll
        for (int it = 0; it < 16; ++it) {
            int idx = tid + it * 256;          // 4096 = 64 rows x 64 col4s
            int row = idx >> 6, c4 = idx & 63;
            *(float4*)(yb + (size_t)row * DIM + c4 * 4) =
                *(const float4*)(scanb + row * 260 + c4 * 4);
        }
    }
}

// ---------------------------------------------------------------------------

extern "C" void kernel_launch(void* const* d_in, const int* in_sizes, int n_in,
                              void* d_out, int out_size)
{
    const float* U  = (const float*)d_in[0];
    const float* A  = (const float*)d_in[1];
    const float* Bm = (const float*)d_in[2];
    const float* Cm = (const float*)d_in[3];
    const float* h0 = (const float*)d_in[4];
    float* Y = (float*)d_out;
    (void)in_sizes; (void)n_in; (void)out_size;

    cudaFuncSetAttribute(kA, cudaFuncAttributeMaxDynamicSharedMemorySize, SMEM_SZ);
    cudaFuncSetAttribute(kB, cudaFuncAttributeMaxDynamicSharedMemorySize, SMEM_SZ);

    k0_convert<<<128, 256>>>(Bm, Cm);
    kA<<<dim3(NC, BATCH), 256, SMEM_SZ>>>(U, A);
    k2_carry<<<BATCH, DIM>>>(A, h0);
    kB<<<dim3(NC, BATCH), 256, SMEM_SZ>>>(A, Y);
}

// round 8
// speedup vs baseline: 2.8327x; 1.2829x over previous
#include <cuda_runtime.h>
#include <cuda_bf16.h>
#include <cstdint>

#define BATCH 16
#define TSEQ  4096
#define DIM   256
#define CH    64
#define NC    (TSEQ/CH)          // 64 chunks

typedef unsigned int u32;
typedef unsigned short u16;

// ---------------- device scratch (allocation-free rule) ----------------
__device__ float g_H[(size_t)BATCH * TSEQ * DIM];   // local-scan h (64 MB)
__device__ float g_E[BATCH * NC * DIM];             // chunk-final local h
// B / C pre-converted bf16 hi/lo in mma fragment layout:
// [variant2][ks16][nt2_16][lane32][slot4]   (16*16*32*4 = 32768 u32 / variant)
__device__ __align__(16) u32 g_Bf[2 * 32768];
__device__ __align__(16) u32 g_Cf[2 * 32768];

// ---------------- helpers ----------------
__device__ __forceinline__ void split_bf16(float x, u16& hi, u16& lo) {
    __nv_bfloat16 h = __float2bfloat16_rn(x);
    __nv_bfloat16 l = __float2bfloat16_rn(x - __bfloat162float(h));
    hi = __bfloat16_as_ushort(h);
    lo = __bfloat16_as_ushort(l);
}
__device__ __forceinline__ u32 pack2(u16 a, u16 b) {
    return (u32)a | ((u32)b << 16);
}
__device__ __forceinline__ void mma_bf16(float* c, const u32* a, u32 b0, u32 b1) {
    asm("mma.sync.aligned.m16n8k16.row.col.f32.bf16.bf16.f32 "
        "{%0,%1,%2,%3}, {%4,%5,%6,%7}, {%8,%9}, {%0,%1,%2,%3};"
        : "+f"(c[0]), "+f"(c[1]), "+f"(c[2]), "+f"(c[3])
        : "r"(a[0]), "r"(a[1]), "r"(a[2]), "r"(a[3]), "r"(b0), "r"(b1));
}

// ---------------------------------------------------------------------------
// k0: convert B and C to hi/lo bf16 fragment layout. 32768 threads.
// ---------------------------------------------------------------------------
__global__ void k0_convert(const float* __restrict__ Bm, const float* __restrict__ Cm)
{
    int idx = blockIdx.x * 256 + threadIdx.x;        // 0..32767
    int slot  = idx & 3;
    int lane  = (idx >> 2) & 31;
    int nt2   = (idx >> 7) & 15;
    int ks    = (idx >> 11) & 15;                    // k-step 0..15
    int ntlow = slot >> 1, breg = slot & 1;
    int n = (nt2 * 2 + ntlow) * 8 + (lane >> 2);
    int k = ks * 16 + (lane & 3) * 2 + breg * 8;

    u16 h0, l0, h1, l1;
    float b0 = Bm[(size_t)k * DIM + n], b1 = Bm[(size_t)(k + 1) * DIM + n];
    split_bf16(b0, h0, l0); split_bf16(b1, h1, l1);
    g_Bf[idx]         = pack2(h0, h1);
    g_Bf[32768 + idx] = pack2(l0, l1);

    float c0 = Cm[(size_t)k * DIM + n], c1 = Cm[(size_t)(k + 1) * DIM + n];
    split_bf16(c0, h0, l0); split_bf16(c1, h1, l1);
    g_Cf[idx]         = pack2(h0, h1);
    g_Cf[32768 + idx] = pack2(l0, l1);
}

// ---------------- smem ----------------
// frag region: UH 32KB + UL 32KB = 65536; scanb (64 x 260 floats = 66560) overlays
#define SMEM_SZ  66560

// A-frag staging: frag index = ((slab*16 + ks)*32 + lane)*4 + reg
__device__ __forceinline__ void stage_A_pair(u32* UH, u32* UL, int row, int cp,
                                             float x, float y)
{
    int slab = row >> 4, rin = row & 15;
    int ks = cp >> 3, cpin = cp & 7;
    int lane = (rin & 7) * 4 + (cpin & 3);
    int reg  = ((cpin >> 2) << 1) | (rin >> 3);
    int a = (((slab * 16 + ks) * 32 + lane) << 2) + reg;
    u16 hx, lx, hy, ly;
    split_bf16(x, hx, lx); split_bf16(y, hy, ly);
    UH[a] = pack2(hx, hy);
    UL[a] = pack2(lx, ly);
}

// Mainloop: warp tile m32 x n64 (2 M-slabs), B-frags JIT via LDG (L1/L2-resident).
// wr = slab pair (0..1), wc = col quarter (0..3). 48 MMAs per warp per ks.
__device__ __forceinline__ void gemm_main(const u32* __restrict__ gBf,
                                          const u32* UH, const u32* UL,
                                          float acc[2][8][4], int wr, int wc, int lane)
{
    const u32* ah0_p = UH + ((((wr * 2 + 0) * 16) * 32 + lane) << 2);
    const u32* ah1_p = UH + ((((wr * 2 + 1) * 16) * 32 + lane) << 2);
    const u32* al0_p = UL + ((((wr * 2 + 0) * 16) * 32 + lane) << 2);
    const u32* al1_p = UL + ((((wr * 2 + 1) * 16) * 32 + lane) << 2);
    const u32* b_p   = gBf + (wc * 4) * 128 + lane * 4;
    #pragma unroll
    for (int ks = 0; ks < 16; ++ks) {
        uint4 AH0 = *(const uint4*)(ah0_p + ks * 128);
        uint4 AL0 = *(const uint4*)(al0_p + ks * 128);
        uint4 AH1 = *(const uint4*)(ah1_p + ks * 128);
        uint4 AL1 = *(const uint4*)(al1_p + ks * 128);
        u32 ah[2][4] = {{AH0.x, AH0.y, AH0.z, AH0.w}, {AH1.x, AH1.y, AH1.z, AH1.w}};
        u32 al[2][4] = {{AL0.x, AL0.y, AL0.z, AL0.w}, {AL1.x, AL1.y, AL1.z, AL1.w}};
        const u32* bp = b_p + ks * 2048;
        #pragma unroll
        for (int jp = 0; jp < 2; ++jp) {
            uint4 BH0 = *(const uint4*)(bp + (2 * jp) * 128);
            uint4 BH1 = *(const uint4*)(bp + (2 * jp + 1) * 128);
            uint4 BL0 = *(const uint4*)(bp + 32768 + (2 * jp) * 128);
            uint4 BL1 = *(const uint4*)(bp + 32768 + (2 * jp + 1) * 128);
            #pragma unroll
            for (int s = 0; s < 2; ++s) {
                float* a0 = acc[s][4 * jp + 0];
                float* a1 = acc[s][4 * jp + 1];
                float* a2 = acc[s][4 * jp + 2];
                float* a3 = acc[s][4 * jp + 3];
                // three passes, acc reuse distance 4
                mma_bf16(a0, ah[s], BH0.x, BH0.y);
                mma_bf16(a1, ah[s], BH0.z, BH0.w);
                mma_bf16(a2, ah[s], BH1.x, BH1.y);
                mma_bf16(a3, ah[s], BH1.z, BH1.w);
                mma_bf16(a0, ah[s], BL0.x, BL0.y);
                mma_bf16(a1, ah[s], BL0.z, BL0.w);
                mma_bf16(a2, ah[s], BL1.x, BL1.y);
                mma_bf16(a3, ah[s], BL1.z, BL1.w);
                mma_bf16(a0, al[s], BH0.x, BH0.y);
                mma_bf16(a1, al[s], BH0.z, BH0.w);
                mma_bf16(a2, al[s], BH1.x, BH1.y);
                mma_bf16(a3, al[s], BH1.z, BH1.w);
            }
        }
    }
}

// write accumulators into scan-layout smem [row][col], row stride 260 floats
__device__ __forceinline__ void acc_to_scanb(float* scanb, float acc[2][8][4],
                                             int wr, int wc, int lane)
{
    #pragma unroll
    for (int s = 0; s < 2; ++s) {
        int r0 = (wr * 2 + s) * 16 + (lane >> 2);
        #pragma unroll
        for (int a = 0; a < 8; ++a) {
            int col = wc * 64 + (a >> 1) * 16 + (a & 1) * 8 + (lane & 3) * 2;
            scanb[r0 * 260 + col]           = acc[s][a][0];
            scanb[r0 * 260 + col + 1]       = acc[s][a][1];
            scanb[(r0 + 8) * 260 + col]     = acc[s][a][2];
            scanb[(r0 + 8) * 260 + col + 1] = acc[s][a][3];
        }
    }
}

// ---------------------------------------------------------------------------
// kA: Bu = U @ B (bf16-split HMMA) fused with local chunk scan. 256 thr, 2 CTA/SM.
// ---------------------------------------------------------------------------
__global__ __launch_bounds__(256, 2) void kA(
    const float* __restrict__ U, const float* __restrict__ A)
{
    extern __shared__ __align__(16) char smem[];
    u32* UH = (u32*)smem;
    u32* UL = UH + 8192;
    float* scanb = (float*)smem;     // overlays frag region after GEMM

    const int tid = threadIdx.x, wid = tid >> 5, lane = tid & 31;
    const int wr = wid & 1, wc = wid >> 1;
    const int b = blockIdx.y, c = blockIdx.x;
    const int t0 = c * CH;

    // stage U tile as hi/lo A-fragments (coalesced float2 reads)
    {
        const float* ub = U + ((size_t)b * TSEQ + t0) * DIM;
        #pragma unroll
        for (int it = 0; it < 32; ++it) {
            int idx = tid + it * 256;          // 8192 = 64 rows x 128 colpairs
            int row = idx >> 7, cp = idx & 127;
            float2 v = *(const float2*)(ub + (size_t)row * DIM + cp * 2);
            stage_A_pair(UH, UL, row, cp, v.x, v.y);
        }
    }
    __syncthreads();

    float acc[2][8][4];
    #pragma unroll
    for (int s = 0; s < 2; ++s)
        #pragma unroll
        for (int i = 0; i < 8; ++i) {
            acc[s][i][0]=0.f; acc[s][i][1]=0.f; acc[s][i][2]=0.f; acc[s][i][3]=0.f;
        }

    gemm_main(g_Bf, UH, UL, acc, wr, wc, lane);

    __syncthreads();                 // frag region dead; reuse as scan buffer
    acc_to_scanb(scanb, acc, wr, wc, lane);
    __syncthreads();

    // local scan: one thread per state
    {
        const int s = tid;
        const float a = A[s];
        float h = 0.f;
        float* hout = g_H + ((size_t)b * TSEQ + t0) * DIM + s;
        #pragma unroll 8
        for (int t = 0; t < CH; ++t) {
            h = fmaf(h, a, scanb[t * 260 + s]);
            hout[(size_t)t * DIM] = h;
        }
        g_E[((size_t)b * NC + c) * DIM + s] = h;
    }
}

// ---------------------------------------------------------------------------
// kB: carry computed inline (scan of g_E), h = local + a^{t+1}*carry -> frags,
//     Y = h @ C. 256 thr, 2 CTA/SM.
// ---------------------------------------------------------------------------
__global__ __launch_bounds__(256, 2) void kB(
    const float* __restrict__ A, const float* __restrict__ h0v,
    float* __restrict__ Y)
{
    extern __shared__ __align__(16) char smem[];
    u32* UH = (u32*)smem;
    u32* UL = UH + 8192;
    float* scanb = (float*)smem;     // overlays frag region after GEMM

    const int tid = threadIdx.x, wid = tid >> 5, lane = tid & 31;
    const int wr = wid & 1, wc = wid >> 1;
    const int b = blockIdx.y, c = blockIdx.x;
    const int t0 = c * CH;

    // phase 1: inline carry scan + fixup into frag layout. All 256 threads:
    // thread = (state pair sp, time half th).
    {
        const int sp = tid & 127;
        const int th = tid >> 7;
        const float2 a2 = *(const float2*)(A + 2 * sp);
        // p = a^64 (exact squarings, same recurrence as old k2)
        float px = a2.x, py = a2.y;
        #pragma unroll
        for (int i = 0; i < 6; ++i) { px *= px; py *= py; }
        float cx = h0v[2 * sp], cy = h0v[2 * sp + 1];
        const float* Eb = g_E + (size_t)b * NC * DIM + 2 * sp;
        for (int j = 0; j < c; ++j) {
            float2 e = *(const float2*)(Eb + (size_t)j * DIM);
            cx = fmaf(px, cx, e.x);
            cy = fmaf(py, cy, e.y);
        }
        // f = a^(t+1): th=0 starts at 1, th=1 starts at a^32
        float fx = 1.f, fy = 1.f;
        if (th) {
            fx = a2.x; fy = a2.y;
            #pragma unroll
            for (int i = 0; i < 5; ++i) { fx *= fx; fy *= fy; }
        }
        const float* hloc = g_H + ((size_t)b * TSEQ + t0 + th * 32) * DIM + 2 * sp;
        #pragma unroll 8
        for (int t = 0; t < 32; ++t) {
            fx *= a2.x; fy *= a2.y;
            float2 hl = *(const float2*)(hloc + (size_t)t * DIM);
            stage_A_pair(UH, UL, th * 32 + t, sp,
                         fmaf(fx, cx, hl.x), fmaf(fy, cy, hl.y));
        }
    }
    __syncthreads();

    float acc[2][8][4];
    #pragma unroll
    for (int s = 0; s < 2; ++s)
        #pragma unroll
        for (int i = 0; i < 8; ++i) {
            acc[s][i][0]=0.f; acc[s][i][1]=0.f; acc[s][i][2]=0.f; acc[s][i][3]=0.f;
        }

    gemm_main(g_Cf, UH, UL, acc, wr, wc, lane);

    __syncthreads();
    acc_to_scanb(scanb, acc, wr, wc, lane);
    __syncthreads();

    // coalesced float4 store of Y tile
    {
        float* yb = Y + ((size_t)b * TSEQ + t0) * DIM;
        #pragma unroll
        for (int it = 0; it < 16; ++it) {
            int idx = tid + it * 256;          // 4096 = 64 rows x 64 col4s
            int row = idx >> 6, c4 = idx & 63;
            *(float4*)(yb + (size_t)row * DIM + c4 * 4) =
                *(const float4*)(scanb + row * 260 + c4 * 4);
        }
    }
}

// ---------------------------------------------------------------------------

extern "C" void kernel_launch(void* const* d_in, const int* in_sizes, int n_in,
                              void* d_out, int out_size)
{
    const float* U  = (const float*)d_in[0];
    const float* A  = (const float*)d_in[1];
    const float* Bm = (const float*)d_in[2];
    const float* Cm = (const float*)d_in[3];
    const float* h0 = (const float*)d_in[4];
    float* Y = (float*)d_out;
    (void)in_sizes; (void)n_in; (void)out_size;

    cudaFuncSetAttribute(kA, cudaFuncAttributeMaxDynamicSharedMemorySize, SMEM_SZ);
    cudaFuncSetAttribute(kB, cudaFuncAttributeMaxDynamicSharedMemorySize, SMEM_SZ);

    k0_convert<<<128, 256>>>(Bm, Cm);
    kA<<<dim3(NC, BATCH), 256, SMEM_SZ>>>(U, A);
    kB<<<dim3(NC, BATCH), 256, SMEM_SZ>>>(A, h0, Y);
}